// round 15
// baseline (speedup 1.0000x reference)
#include <cuda_runtime.h>

#define BB 1024
#define DD 128
#define TT 256
#define HH 64
#define GG 256  // 4*H

typedef unsigned long long ull;

__device__ float g_xp0[(size_t)BB * TT * GG];

__device__ __forceinline__ void ffma2(ull& d, ull a, ull b) {
    asm("fma.rn.f32x2 %0, %1, %2, %0;" : "+l"(d) : "l"(a), "l"(b));
}
__device__ __forceinline__ float2 u2f(ull u) {
    float2 r;
    r.x = __uint_as_float((unsigned)(u & 0xffffffffULL));
    r.y = __uint_as_float((unsigned)(u >> 32));
    return r;
}

__device__ __forceinline__ float sigm(float x) {
    return __fdividef(1.0f, 1.0f + __expf(-x));
}
__device__ __forceinline__ float tanh_acc(float x) {
    float a = fabsf(x);
    float e = __expf(-2.0f * a);
    float r = (1.0f - e) * __fdividef(1.0f, 1.0f + e);
    return copysignf(r, x);
}

// ---------------------------------------------------------------------------
// Kernel 1: xp0[b,t,g] = sum_d x[b,d,t] * w_ih0[g,d] + bias[g]
// (byte-identical to the R3 winner; ~455us)
// ---------------------------------------------------------------------------
__global__ __launch_bounds__(256) void k_inproj(
    const float* __restrict__ x,
    const float* __restrict__ w_ih0,
    const float* __restrict__ b_ih0,
    const float* __restrict__ b_hh0)
{
    extern __shared__ float sm[];
    float* wt = sm;              // [128][260]
    float* xd = sm + 128 * 260;  // [128][64] of float2 {v, v}

    const int tid = threadIdx.x;
    const int b   = blockIdx.x;

    {
        const float4* w4 = (const float4*)w_ih0;
        #pragma unroll
        for (int i = 0; i < 32; i++) {
            int j  = tid + i * 256;
            int g  = j >> 5;
            int dq = j & 31;
            float4 v = w4[j];
            wt[(4 * dq + 0) * 260 + g] = v.x;
            wt[(4 * dq + 1) * 260 + g] = v.y;
            wt[(4 * dq + 2) * 260 + g] = v.z;
            wt[(4 * dq + 3) * 260 + g] = v.w;
        }
    }

    const int tx = tid & 31;
    const int ty = tid >> 5;

    const float4* bi4 = (const float4*)b_ih0;
    const float4* bh4 = (const float4*)b_hh0;
    float4 bia = bi4[tx],      bha = bh4[tx];
    float4 bib = bi4[32 + tx], bhb = bh4[32 + tx];
    float blo[4] = {bia.x + bha.x, bia.y + bha.y, bia.z + bha.z, bia.w + bha.w};
    float bhi[4] = {bib.x + bhb.x, bib.y + bhb.y, bib.z + bhb.z, bib.w + bhb.w};

    for (int tt = 0; tt < 4; tt++) {
        const int t0 = tt * 64;
        __syncthreads();
        {
            const float* xb = x + (size_t)b * DD * TT + t0;
            int t = tid & 63, d0 = tid >> 6;
            #pragma unroll
            for (int d = d0; d < 128; d += 4) {
                float v = xb[d * TT + t];
                ((float2*)xd)[d * 64 + t] = make_float2(v, v);
            }
        }
        __syncthreads();

        ull acc[8][4];
        #pragma unroll
        for (int a = 0; a < 8; a++)
            #pragma unroll
            for (int e = 0; e < 4; e++) acc[a][e] = 0ULL;

        #pragma unroll 4
        for (int d = 0; d < 128; d++) {
            ulonglong2 x01 = *(const ulonglong2*)&xd[(d * 64 + ty * 4) * 2];
            ulonglong2 x23 = *(const ulonglong2*)&xd[(d * 64 + ty * 4 + 2) * 2];
            ulonglong2 x45 = *(const ulonglong2*)&xd[(d * 64 + 32 + ty * 4) * 2];
            ulonglong2 x67 = *(const ulonglong2*)&xd[(d * 64 + 32 + ty * 4 + 2) * 2];
            ulonglong2 wa = *(const ulonglong2*)&wt[d * 260 + tx * 4];
            ulonglong2 wb = *(const ulonglong2*)&wt[d * 260 + 128 + tx * 4];
            ull xv[8] = {x01.x, x01.y, x23.x, x23.y, x45.x, x45.y, x67.x, x67.y};
            ull wp[4] = {wa.x, wa.y, wb.x, wb.y};
            #pragma unroll
            for (int a = 0; a < 8; a++)
                #pragma unroll
                for (int e = 0; e < 4; e++)
                    ffma2(acc[a][e], xv[a], wp[e]);
        }

        #pragma unroll
        for (int a = 0; a < 8; a++) {
            int t = (a < 4) ? (ty * 4 + a) : (32 + ty * 4 + (a - 4));
            float* row = g_xp0 + ((size_t)b * TT + t0 + t) * GG;
            float2 p0 = u2f(acc[a][0]), p1 = u2f(acc[a][1]);
            float2 p2 = u2f(acc[a][2]), p3 = u2f(acc[a][3]);
            float4 lo = make_float4(p0.x + blo[0], p0.y + blo[1],
                                    p1.x + blo[2], p1.y + blo[3]);
            float4 hi = make_float4(p2.x + bhi[0], p2.y + bhi[1],
                                    p3.x + bhi[2], p3.y + bhi[3]);
            *(float4*)(row + tx * 4)       = lo;
            *(float4*)(row + 128 + tx * 4) = hi;
        }
    }
}

// ---------------------------------------------------------------------------
// Kernel 2: layer-pipelined fused LSTM, 512 threads (16 warps/SM).
// Thread = (gate g = tid&255, batch-half bh = tid>>8) -> 4 batch rows each.
// Batch split has NO cross-thread reduction; per-thread regs ~halved vs the
// 8-row version, so 16 warps fit under the 128-reg cap (lb 512,1).
// ---------------------------------------------------------------------------
#define W0OFF 0
#define W1OFF 16384
#define W2OFF 32768
#define H0OFF 49152
#define H1OFF 49664
#define GS0OFF 50176
#define GS1OFF 52480
#define SMFL   54784

__device__ __forceinline__ void cell_upd1(const float* __restrict__ gsm,
                                          float* __restrict__ hs,
                                          int b, int h, float& c)
{
    float ig = gsm[h * 9 + b];
    float fg = gsm[(64 + h) * 9 + b];
    float gg = gsm[(128 + h) * 9 + b];
    float og = gsm[(192 + h) * 9 + b];
    c = sigm(fg) * c + sigm(ig) * tanh_acc(gg);
    hs[b * 64 + h] = sigm(og) * tanh_acc(c);
}

__global__ __launch_bounds__(512, 1) void k_lstm(
    const float* __restrict__ w_hh0,
    const float* __restrict__ w_ih1,
    const float* __restrict__ b_ih1,
    const float* __restrict__ b_hh1,
    const float* __restrict__ w_hh1,
    const float* __restrict__ w_fc,
    const float* __restrict__ b_fc,
    float* __restrict__ out)
{
    extern __shared__ float sm[];
    float* w0q = sm + W0OFF;   // [16 k4][256 g] float4
    float* w1q = sm + W1OFF;
    float* w2q = sm + W2OFF;
    float* h0f = sm + H0OFF;   // [8 b][64 h]
    float* h1f = sm + H1OFF;
    float* gs0 = sm + GS0OFF;  // [256 g][9]
    float* gs1 = sm + GS1OFF;

    const int tid = threadIdx.x;
    const int b0  = blockIdx.x * 8;
    const int g   = tid & 255;    // gate column
    const int bh  = tid >> 8;     // batch half: rows 4bh..4bh+3

    // Repack [256 g][64 k] weights -> [k4][g] float4
    {
        const float4* a4 = (const float4*)w_hh0;
        const float4* b4 = (const float4*)w_ih1;
        const float4* c4 = (const float4*)w_hh1;
        #pragma unroll
        for (int i = 0; i < 8; i++) {
            int j  = tid + i * 512;        // 0..4095
            int gg = j >> 4;
            int k4 = j & 15;
            ((float4*)w0q)[k4 * 256 + gg] = a4[j];
            ((float4*)w1q)[k4 * 256 + gg] = b4[j];
            ((float4*)w2q)[k4 * 256 + gg] = c4[j];
        }
    }
    if (tid < 512) { h0f[tid] = 0.0f; h1f[tid] = 0.0f; }

    const float bias1 = b_ih1[g] + b_hh1[g];

    // Cell ownership: 1 cell per thread per layer (b = tid>>6, h = tid&63)
    const int cB = tid >> 6;
    const int cH = tid & 63;
    float c0 = 0.0f, c1 = 0.0f;

    const float* xp = g_xp0 + (size_t)(b0 + 4 * bh) * TT * GG + g;

    float xv[4];
    #pragma unroll
    for (int j = 0; j < 4; j++) xv[j] = xp[(size_t)j * TT * GG];  // xp(0)

    __syncthreads();

    // pre-step: gates0(0) = xp(0)  (h0(-1) = 0)
    #pragma unroll
    for (int j = 0; j < 4; j++) gs0[g * 9 + 4 * bh + j] = xv[j];
    #pragma unroll
    for (int j = 0; j < 4; j++)
        xv[j] = xp[((size_t)j * TT + 1) * GG];  // prefetch xp(1)
    __syncthreads();
    cell_upd1(gs0, h0f, cB, cH, c0);            // -> h0(0)
    __syncthreads();

    for (int p = 0; p < 255; p++) {
        {   // A-GEMM: gates0(p+1) = xp(p+1) + h0(p) @ w_hh0^T
            ull acc[4];
            #pragma unroll
            for (int j = 0; j < 4; j++) acc[j] = 0ULL;
            #pragma unroll 4
            for (int k4 = 0; k4 < 16; k4++) {
                ulonglong2 w = *(const ulonglong2*)&w0q[k4 * 1024 + g * 4];
                #pragma unroll
                for (int j = 0; j < 4; j++) {
                    ulonglong2 h = *(const ulonglong2*)&h0f[(4 * bh + j) * 64 + k4 * 4];
                    ffma2(acc[j], h.x, w.x);
                    ffma2(acc[j], h.y, w.y);
                }
            }
            #pragma unroll
            for (int j = 0; j < 4; j++) {
                float2 s = u2f(acc[j]);
                gs0[g * 9 + 4 * bh + j] = xv[j] + s.x + s.y;
            }
        }
        {   // C-GEMM: gates1(p) = bias1 + h0(p) @ w_ih1^T + h1(p-1) @ w_hh1^T
            ull acc[4];
            #pragma unroll
            for (int j = 0; j < 4; j++) acc[j] = 0ULL;
            #pragma unroll 4
            for (int k4 = 0; k4 < 16; k4++) {
                ulonglong2 wa = *(const ulonglong2*)&w1q[k4 * 1024 + g * 4];
                ulonglong2 wb = *(const ulonglong2*)&w2q[k4 * 1024 + g * 4];
                #pragma unroll
                for (int j = 0; j < 4; j++) {
                    ulonglong2 ha = *(const ulonglong2*)&h0f[(4 * bh + j) * 64 + k4 * 4];
                    ulonglong2 hb = *(const ulonglong2*)&h1f[(4 * bh + j) * 64 + k4 * 4];
                    ffma2(acc[j], ha.x, wa.x);
                    ffma2(acc[j], ha.y, wa.y);
                    ffma2(acc[j], hb.x, wb.x);
                    ffma2(acc[j], hb.y, wb.y);
                }
            }
            #pragma unroll
            for (int j = 0; j < 4; j++) {
                float2 s = u2f(acc[j]);
                gs1[g * 9 + 4 * bh + j] = bias1 + s.x + s.y;
            }
        }
        {   // prefetch xp(p+2)
            int tn = (p + 2 < TT) ? p + 2 : TT - 1;
            #pragma unroll
            for (int j = 0; j < 4; j++)
                xv[j] = xp[((size_t)j * TT + tn) * GG];
        }
        __syncthreads();  // (1)
        cell_upd1(gs0, h0f, cB, cH, c0);   // -> h0(p+1)
        cell_upd1(gs1, h1f, cB, cH, c1);   // -> h1(p)
        __syncthreads();  // (2)
    }

    {   // epilogue: gates1(255) from h0(255), h1(254)
        ull acc[4];
        #pragma unroll
        for (int j = 0; j < 4; j++) acc[j] = 0ULL;
        #pragma unroll 4
        for (int k4 = 0; k4 < 16; k4++) {
            ulonglong2 wa = *(const ulonglong2*)&w1q[k4 * 1024 + g * 4];
            ulonglong2 wb = *(const ulonglong2*)&w2q[k4 * 1024 + g * 4];
            #pragma unroll
            for (int j = 0; j < 4; j++) {
                ulonglong2 ha = *(const ulonglong2*)&h0f[(4 * bh + j) * 64 + k4 * 4];
                ulonglong2 hb = *(const ulonglong2*)&h1f[(4 * bh + j) * 64 + k4 * 4];
                ffma2(acc[j], ha.x, wa.x);
                ffma2(acc[j], ha.y, wa.y);
                ffma2(acc[j], hb.x, wb.x);
                ffma2(acc[j], hb.y, wb.y);
            }
        }
        #pragma unroll
        for (int j = 0; j < 4; j++) {
            float2 s = u2f(acc[j]);
            gs1[g * 9 + 4 * bh + j] = bias1 + s.x + s.y;
        }
    }
    __syncthreads();
    cell_upd1(gs1, h1f, cB, cH, c1);       // -> h1(255)
    __syncthreads();

    // Head: scores[b, :] = hT @ w_fc^T + b_fc
    float* wfct = w0q;  // reuse (fully synced): [k][o], 64x128
    for (int i = tid; i < 128 * 64; i += 512) {
        int o = i >> 6, k = i & 63;
        wfct[k * 128 + o] = w_fc[i];
    }
    __syncthreads();

    #pragma unroll
    for (int q = 0; q < 2; q++) {
        int p  = tid + q * 512;   // 0..1023
        int bo = p >> 7;          // batch row 0..7
        int o  = p & 127;         // output feature
        float acc = b_fc[o];
        #pragma unroll 4
        for (int k = 0; k < 64; k++)
            acc += h1f[bo * 64 + k] * wfct[k * 128 + o];
        out[(size_t)(b0 + bo) * 128 + o] = acc;
    }
}

extern "C" void kernel_launch(void* const* d_in, const int* in_sizes, int n_in,
                              void* d_out, int out_size)
{
    const float* x     = (const float*)d_in[0];
    const float* w_ih0 = (const float*)d_in[1];
    const float* w_hh0 = (const float*)d_in[2];
    const float* b_ih0 = (const float*)d_in[3];
    const float* b_hh0 = (const float*)d_in[4];
    const float* w_ih1 = (const float*)d_in[5];
    const float* w_hh1 = (const float*)d_in[6];
    const float* b_ih1 = (const float*)d_in[7];
    const float* b_hh1 = (const float*)d_in[8];
    const float* w_fc  = (const float*)d_in[9];
    const float* b_fc  = (const float*)d_in[10];
    float* out = (float*)d_out;

    const int smem1 = (128 * 260 + 128 * 64 * 2) * 4;  // 198656
    const int smem2 = SMFL * 4;                        // 219136

    cudaFuncSetAttribute(k_inproj, cudaFuncAttributeMaxDynamicSharedMemorySize, smem1);
    cudaFuncSetAttribute(k_lstm,   cudaFuncAttributeMaxDynamicSharedMemorySize, smem2);

    k_inproj<<<1024, 256, smem1>>>(x, w_ih0, b_ih0, b_hh0);
    k_lstm<<<128, 512, smem2>>>(w_hh0, w_ih1, b_ih1, b_hh1, w_hh1, w_fc, b_fc, out);
}

// round 17
// speedup vs baseline: 1.7754x; 1.7754x over previous
#include <cuda_runtime.h>

#define BB 1024
#define DD 128
#define TT 256
#define HH 64
#define GG 256  // 4*H

typedef unsigned long long ull;

__device__ float g_xp0[(size_t)BB * TT * GG];

__device__ __forceinline__ void ffma2(ull& d, ull a, ull b) {
    asm("fma.rn.f32x2 %0, %1, %2, %0;" : "+l"(d) : "l"(a), "l"(b));
}
__device__ __forceinline__ float2 u2f(ull u) {
    float2 r;
    r.x = __uint_as_float((unsigned)(u & 0xffffffffULL));
    r.y = __uint_as_float((unsigned)(u >> 32));
    return r;
}

__device__ __forceinline__ float sigm(float x) {
    return __fdividef(1.0f, 1.0f + __expf(-x));
}
__device__ __forceinline__ float tanh_acc(float x) {
    float a = fabsf(x);
    float e = __expf(-2.0f * a);
    float r = (1.0f - e) * __fdividef(1.0f, 1.0f + e);
    return copysignf(r, x);
}

// ---------------------------------------------------------------------------
// Kernel 1: xp0[b,t,g] = sum_d x[b,d,t] * w_ih0[g,d] + bias[g]
// (byte-identical to the R3 winner; ~455us)
// ---------------------------------------------------------------------------
__global__ __launch_bounds__(256) void k_inproj(
    const float* __restrict__ x,
    const float* __restrict__ w_ih0,
    const float* __restrict__ b_ih0,
    const float* __restrict__ b_hh0)
{
    extern __shared__ float sm[];
    float* wt = sm;              // [128][260]
    float* xd = sm + 128 * 260;  // [128][64] of float2 {v, v}

    const int tid = threadIdx.x;
    const int b   = blockIdx.x;

    {
        const float4* w4 = (const float4*)w_ih0;
        #pragma unroll
        for (int i = 0; i < 32; i++) {
            int j  = tid + i * 256;
            int g  = j >> 5;
            int dq = j & 31;
            float4 v = w4[j];
            wt[(4 * dq + 0) * 260 + g] = v.x;
            wt[(4 * dq + 1) * 260 + g] = v.y;
            wt[(4 * dq + 2) * 260 + g] = v.z;
            wt[(4 * dq + 3) * 260 + g] = v.w;
        }
    }

    const int tx = tid & 31;
    const int ty = tid >> 5;

    const float4* bi4 = (const float4*)b_ih0;
    const float4* bh4 = (const float4*)b_hh0;
    float4 bia = bi4[tx],      bha = bh4[tx];
    float4 bib = bi4[32 + tx], bhb = bh4[32 + tx];
    float blo[4] = {bia.x + bha.x, bia.y + bha.y, bia.z + bha.z, bia.w + bha.w};
    float bhi[4] = {bib.x + bhb.x, bib.y + bhb.y, bib.z + bhb.z, bib.w + bhb.w};

    for (int tt = 0; tt < 4; tt++) {
        const int t0 = tt * 64;
        __syncthreads();
        {
            const float* xb = x + (size_t)b * DD * TT + t0;
            int t = tid & 63, d0 = tid >> 6;
            #pragma unroll
            for (int d = d0; d < 128; d += 4) {
                float v = xb[d * TT + t];
                ((float2*)xd)[d * 64 + t] = make_float2(v, v);
            }
        }
        __syncthreads();

        ull acc[8][4];
        #pragma unroll
        for (int a = 0; a < 8; a++)
            #pragma unroll
            for (int e = 0; e < 4; e++) acc[a][e] = 0ULL;

        #pragma unroll 4
        for (int d = 0; d < 128; d++) {
            ulonglong2 x01 = *(const ulonglong2*)&xd[(d * 64 + ty * 4) * 2];
            ulonglong2 x23 = *(const ulonglong2*)&xd[(d * 64 + ty * 4 + 2) * 2];
            ulonglong2 x45 = *(const ulonglong2*)&xd[(d * 64 + 32 + ty * 4) * 2];
            ulonglong2 x67 = *(const ulonglong2*)&xd[(d * 64 + 32 + ty * 4 + 2) * 2];
            ulonglong2 wa = *(const ulonglong2*)&wt[d * 260 + tx * 4];
            ulonglong2 wb = *(const ulonglong2*)&wt[d * 260 + 128 + tx * 4];
            ull xv[8] = {x01.x, x01.y, x23.x, x23.y, x45.x, x45.y, x67.x, x67.y};
            ull wp[4] = {wa.x, wa.y, wb.x, wb.y};
            #pragma unroll
            for (int a = 0; a < 8; a++)
                #pragma unroll
                for (int e = 0; e < 4; e++)
                    ffma2(acc[a][e], xv[a], wp[e]);
        }

        #pragma unroll
        for (int a = 0; a < 8; a++) {
            int t = (a < 4) ? (ty * 4 + a) : (32 + ty * 4 + (a - 4));
            float* row = g_xp0 + ((size_t)b * TT + t0 + t) * GG;
            float2 p0 = u2f(acc[a][0]), p1 = u2f(acc[a][1]);
            float2 p2 = u2f(acc[a][2]), p3 = u2f(acc[a][3]);
            float4 lo = make_float4(p0.x + blo[0], p0.y + blo[1],
                                    p1.x + blo[2], p1.y + blo[3]);
            float4 hi = make_float4(p2.x + bhi[0], p2.y + bhi[1],
                                    p3.x + bhi[2], p3.y + bhi[3]);
            *(float4*)(row + tx * 4)       = lo;
            *(float4*)(row + 128 + tx * 4) = hi;
        }
    }
}

// ---------------------------------------------------------------------------
// Kernel 2: layer-pipelined fused LSTM, 768 threads = 3 matrix groups.
// group = tid>>8 (0: w0·h0 -> gs0; 1: w1·h0 -> gs1a; 2: w2·h1 -> gs1b).
// Same total FFMA2 + crossbar traffic as the 256-thread version, but 24
// warps/SM (6 per SMSP) to hide LDS latency. Layer-1 gates = gs1a + gs1b.
// smem floats: w0q|w1q|w2q (16384 ea) | h0f[512] | h1f[512] |
//              gs0|gs1a|gs1b (2304 ea) = 57088 floats = 228352 B
// ---------------------------------------------------------------------------
#define W0OFF  0
#define W1OFF  16384
#define W2OFF  32768
#define H0OFF  49152
#define H1OFF  49664
#define GS0OFF 50176
#define GS1AOFF 52480
#define GS1BOFF 54784
#define SMFL    57088

__global__ __launch_bounds__(768, 1) void k_lstm(
    const float* __restrict__ w_hh0,
    const float* __restrict__ w_ih1,
    const float* __restrict__ b_ih1,
    const float* __restrict__ b_hh1,
    const float* __restrict__ w_hh1,
    const float* __restrict__ w_fc,
    const float* __restrict__ b_fc,
    float* __restrict__ out)
{
    extern __shared__ float sm[];
    float* w0q  = sm + W0OFF;    // [16 k4][256 g] float4
    float* w1q  = sm + W1OFF;
    float* w2q  = sm + W2OFF;
    float* h0f  = sm + H0OFF;    // [8 b][64 h]
    float* h1f  = sm + H1OFF;
    float* gs0  = sm + GS0OFF;   // [256 g][9]
    float* gs1a = sm + GS1AOFF;
    float* gs1b = sm + GS1BOFF;

    const int tid   = threadIdx.x;
    const int b0    = blockIdx.x * 8;
    const int g     = tid & 255;   // gate column
    const int grp   = tid >> 8;    // 0, 1, 2

    // Repack [256 g][64 k] weights -> [k4][g] float4
    {
        const float4* a4 = (const float4*)w_hh0;
        const float4* b4 = (const float4*)w_ih1;
        const float4* c4 = (const float4*)w_hh1;
        for (int j = tid; j < 4096; j += 768) {
            int gg = j >> 4;
            int k4 = j & 15;
            ((float4*)w0q)[k4 * 256 + gg] = a4[j];
            ((float4*)w1q)[k4 * 256 + gg] = b4[j];
            ((float4*)w2q)[k4 * 256 + gg] = c4[j];
        }
    }
    if (tid < 512) { h0f[tid] = 0.0f; h1f[tid] = 0.0f; }

    const float bias1 = b_ih1[g] + b_hh1[g];

    // Cell ownership (threads 0..511): b = tid>>6, h = tid&63, both layers
    const int cB = tid >> 6;
    const int cH = tid & 63;
    float c0 = 0.0f, c1 = 0.0f;

    const float* xp = g_xp0 + (size_t)b0 * TT * GG + g;  // used by group 0

    float xv[8];
    if (grp == 0) {
        #pragma unroll
        for (int b = 0; b < 8; b++) xv[b] = xp[(size_t)b * TT * GG];  // xp(0)
    }

    __syncthreads();

    // pre-step: gates0(0) = xp(0)  (h0(-1) = 0); group 0 owns gs0
    if (grp == 0) {
        #pragma unroll
        for (int b = 0; b < 8; b++) gs0[g * 9 + b] = xv[b];
        #pragma unroll
        for (int b = 0; b < 8; b++)
            xv[b] = xp[((size_t)b * TT + 1) * GG];  // prefetch xp(1)
    }
    __syncthreads();
    if (tid < 512) {  // layer-0 cell update -> h0(0)
        float ig = gs0[cH * 9 + cB];
        float fg = gs0[(64 + cH) * 9 + cB];
        float gg = gs0[(128 + cH) * 9 + cB];
        float og = gs0[(192 + cH) * 9 + cB];
        c0 = sigm(fg) * c0 + sigm(ig) * tanh_acc(gg);
        h0f[cB * 64 + cH] = sigm(og) * tanh_acc(c0);
    }
    __syncthreads();

    // main loop: period p -> h0(p+1) and h1(p)
    for (int p = 0; p < 255; p++) {
        if (grp == 0) {
            // gates0(p+1) = xp(p+1) + h0(p) @ w_hh0^T
            ull acc[8];
            #pragma unroll
            for (int b = 0; b < 8; b++) acc[b] = 0ULL;
            #pragma unroll 4
            for (int k4 = 0; k4 < 16; k4++) {
                ulonglong2 w = *(const ulonglong2*)&w0q[k4 * 1024 + g * 4];
                #pragma unroll
                for (int b = 0; b < 8; b++) {
                    ulonglong2 h = *(const ulonglong2*)&h0f[b * 64 + k4 * 4];
                    ffma2(acc[b], h.x, w.x);
                    ffma2(acc[b], h.y, w.y);
                }
            }
            #pragma unroll
            for (int b = 0; b < 8; b++) {
                float2 s = u2f(acc[b]);
                gs0[g * 9 + b] = xv[b] + s.x + s.y;
            }
            // prefetch xp(p+2)
            int tn = (p + 2 < TT) ? p + 2 : TT - 1;
            #pragma unroll
            for (int b = 0; b < 8; b++)
                xv[b] = xp[((size_t)b * TT + tn) * GG];
        } else if (grp == 1) {
            // gs1a = bias1 + h0(p) @ w_ih1^T
            ull acc[8];
            #pragma unroll
            for (int b = 0; b < 8; b++) acc[b] = 0ULL;
            #pragma unroll 4
            for (int k4 = 0; k4 < 16; k4++) {
                ulonglong2 w = *(const ulonglong2*)&w1q[k4 * 1024 + g * 4];
                #pragma unroll
                for (int b = 0; b < 8; b++) {
                    ulonglong2 h = *(const ulonglong2*)&h0f[b * 64 + k4 * 4];
                    ffma2(acc[b], h.x, w.x);
                    ffma2(acc[b], h.y, w.y);
                }
            }
            #pragma unroll
            for (int b = 0; b < 8; b++) {
                float2 s = u2f(acc[b]);
                gs1a[g * 9 + b] = bias1 + s.x + s.y;
            }
        } else {
            // gs1b = h1(p-1) @ w_hh1^T
            ull acc[8];
            #pragma unroll
            for (int b = 0; b < 8; b++) acc[b] = 0ULL;
            #pragma unroll 4
            for (int k4 = 0; k4 < 16; k4++) {
                ulonglong2 w = *(const ulonglong2*)&w2q[k4 * 1024 + g * 4];
                #pragma unroll
                for (int b = 0; b < 8; b++) {
                    ulonglong2 h = *(const ulonglong2*)&h1f[b * 64 + k4 * 4];
                    ffma2(acc[b], h.x, w.x);
                    ffma2(acc[b], h.y, w.y);
                }
            }
            #pragma unroll
            for (int b = 0; b < 8; b++) {
                float2 s = u2f(acc[b]);
                gs1b[g * 9 + b] = s.x + s.y;
            }
        }
        __syncthreads();  // (1)

        if (tid < 512) {
            // layer-0 update -> h0(p+1)
            {
                float ig = gs0[cH * 9 + cB];
                float fg = gs0[(64 + cH) * 9 + cB];
                float gg = gs0[(128 + cH) * 9 + cB];
                float og = gs0[(192 + cH) * 9 + cB];
                c0 = sigm(fg) * c0 + sigm(ig) * tanh_acc(gg);
                h0f[cB * 64 + cH] = sigm(og) * tanh_acc(c0);
            }
            // layer-1 update -> h1(p)
            {
                float ig = gs1a[cH * 9 + cB]         + gs1b[cH * 9 + cB];
                float fg = gs1a[(64 + cH) * 9 + cB]  + gs1b[(64 + cH) * 9 + cB];
                float gg = gs1a[(128 + cH) * 9 + cB] + gs1b[(128 + cH) * 9 + cB];
                float og = gs1a[(192 + cH) * 9 + cB] + gs1b[(192 + cH) * 9 + cB];
                c1 = sigm(fg) * c1 + sigm(ig) * tanh_acc(gg);
                h1f[cB * 64 + cH] = sigm(og) * tanh_acc(c1);
            }
        }
        __syncthreads();  // (2)
    }

    // epilogue: gates1(255) from h0(255), h1(254)
    if (grp == 1) {
        ull acc[8];
        #pragma unroll
        for (int b = 0; b < 8; b++) acc[b] = 0ULL;
        #pragma unroll 4
        for (int k4 = 0; k4 < 16; k4++) {
            ulonglong2 w = *(const ulonglong2*)&w1q[k4 * 1024 + g * 4];
            #pragma unroll
            for (int b = 0; b < 8; b++) {
                ulonglong2 h = *(const ulonglong2*)&h0f[b * 64 + k4 * 4];
                ffma2(acc[b], h.x, w.x);
                ffma2(acc[b], h.y, w.y);
            }
        }
        #pragma unroll
        for (int b = 0; b < 8; b++) {
            float2 s = u2f(acc[b]);
            gs1a[g * 9 + b] = bias1 + s.x + s.y;
        }
    } else if (grp == 2) {
        ull acc[8];
        #pragma unroll
        for (int b = 0; b < 8; b++) acc[b] = 0ULL;
        #pragma unroll 4
        for (int k4 = 0; k4 < 16; k4++) {
            ulonglong2 w = *(const ulonglong2*)&w2q[k4 * 1024 + g * 4];
            #pragma unroll
            for (int b = 0; b < 8; b++) {
                ulonglong2 h = *(const ulonglong2*)&h1f[b * 64 + k4 * 4];
                ffma2(acc[b], h.x, w.x);
                ffma2(acc[b], h.y, w.y);
            }
        }
        #pragma unroll
        for (int b = 0; b < 8; b++) {
            float2 s = u2f(acc[b]);
            gs1b[g * 9 + b] = s.x + s.y;
        }
    }
    __syncthreads();
    if (tid < 512) {  // -> h1(255)
        float ig = gs1a[cH * 9 + cB]         + gs1b[cH * 9 + cB];
        float fg = gs1a[(64 + cH) * 9 + cB]  + gs1b[(64 + cH) * 9 + cB];
        float gg = gs1a[(128 + cH) * 9 + cB] + gs1b[(128 + cH) * 9 + cB];
        float og = gs1a[(192 + cH) * 9 + cB] + gs1b[(192 + cH) * 9 + cB];
        c1 = sigm(fg) * c1 + sigm(ig) * tanh_acc(gg);
        h1f[cB * 64 + cH] = sigm(og) * tanh_acc(c1);
    }
    __syncthreads();

    // Head: scores[b, :] = hT @ w_fc^T + b_fc
    float* wfct = w0q;  // reuse (fully synced): [k][o], 64x128
    for (int i = tid; i < 128 * 64; i += 768) {
        int o = i >> 6, k = i & 63;
        wfct[k * 128 + o] = w_fc[i];
    }
    __syncthreads();

    if (tid < 512) {
        #pragma unroll
        for (int q = 0; q < 2; q++) {
            int p  = tid + q * 512;   // 0..1023
            int bo = p >> 7;          // batch row 0..7
            int o  = p & 127;         // output feature
            float acc = b_fc[o];
            #pragma unroll 4
            for (int k = 0; k < 64; k++)
                acc += h1f[bo * 64 + k] * wfct[k * 128 + o];
            out[(size_t)(b0 + bo) * 128 + o] = acc;
        }
    }
}

extern "C" void kernel_launch(void* const* d_in, const int* in_sizes, int n_in,
                              void* d_out, int out_size)
{
    const float* x     = (const float*)d_in[0];
    const float* w_ih0 = (const float*)d_in[1];
    const float* w_hh0 = (const float*)d_in[2];
    const float* b_ih0 = (const float*)d_in[3];
    const float* b_hh0 = (const float*)d_in[4];
    const float* w_ih1 = (const float*)d_in[5];
    const float* w_hh1 = (const float*)d_in[6];
    const float* b_ih1 = (const float*)d_in[7];
    const float* b_hh1 = (const float*)d_in[8];
    const float* w_fc  = (const float*)d_in[9];
    const float* b_fc  = (const float*)d_in[10];
    float* out = (float*)d_out;

    const int smem1 = (128 * 260 + 128 * 64 * 2) * 4;  // 198656
    const int smem2 = SMFL * 4;                        // 228352

    cudaFuncSetAttribute(k_inproj, cudaFuncAttributeMaxDynamicSharedMemorySize, smem1);
    cudaFuncSetAttribute(k_lstm,   cudaFuncAttributeMaxDynamicSharedMemorySize, smem2);

    k_inproj<<<1024, 256, smem1>>>(x, w_ih0, b_ih0, b_hh0);
    k_lstm<<<128, 768, smem2>>>(w_hh0, w_ih1, b_ih1, b_hh1, w_hh1, w_fc, b_fc, out);
}